// round 7
// baseline (speedup 1.0000x reference)
#include <cuda_runtime.h>
#include <math.h>

// Problem constants
#define S_N   256
#define V_N   200
#define F_N   5
#define G_N   80
#define NT    16
#define NR    5
#define NROT  16
#define EPSF  1e-5f

#define TWO_PI_F 6.28318530717958647692f
#define DTH_F    0.39269908169872415481f
#define LOG2E_F  1.44269504088896340736f

typedef unsigned long long ull;

// Scratch
__device__ float d_GDN[(size_t)S_N * NROT * G_N * 8];   // [s][r][g=p*16+k][8]
__device__ float d_PMAX[(size_t)2 * S_N * 400];         // [half][s][f*80+gp]
__device__ int   d_CTR;                                  // k45 completion counter

// ---------------- packed f32x2 helpers ----------------
__device__ __forceinline__ ull ffma2(ull a, ull b, ull c) {
    ull d;
    asm("fma.rn.f32x2 %0, %1, %2, %3;" : "=l"(d) : "l"(a), "l"(b), "l"(c));
    return d;
}
__device__ __forceinline__ ull pack2(float x) {
    ull d;
    asm("mov.b64 %0, {%1, %1};" : "=l"(d) : "f"(x));
    return d;
}
__device__ __forceinline__ float2 unpack2(ull v) {
    float2 f;
    asm("mov.b64 {%0, %1}, %2;" : "=f"(f.x), "=f"(f.y) : "l"(v));
    return f;
}
__device__ __forceinline__ float ex2f(float x) {
    float r;
    asm("ex2.approx.f32 %0, %1;" : "=f"(r) : "f"(x));
    return r;
}

// ---------------------------------------------------------------------------
// k12: one block per s, 256 threads = (r, k). Full 200-v GEMM per thread with
// FFMA2 accumulation; A rows ping-pong prefetched; thetas batched by float4.
// ---------------------------------------------------------------------------
__global__ __launch_bounds__(256) void k12(const float* __restrict__ feat,
                                           const float* __restrict__ rho,
                                           const float* __restrict__ theta,
                                           const float* __restrict__ mask,
                                           const float* __restrict__ mu_rho,
                                           const float* __restrict__ sigma_rho,
                                           const float* __restrict__ mu_theta,
                                           const float* __restrict__ sigma_theta)
{
    __shared__ float As[(V_N + 1) * 32];   // +1 zero pad row for prefetch overrun
    __shared__ float t_s[V_N];

    int s   = blockIdx.x;
    int tid = threadIdx.x;
    int r   = tid >> 4;
    int k   = tid & 15;

    if (s == 0 && tid == 0) d_CTR = 0;   // reset k45 counter (stream-ordered)

    // theta-gaussian constants
    float mu_k = __ldg(&mu_theta[k]);
    float st   = __ldg(&sigma_theta[k]);
    float sL   = sqrtf(LOG2E_F / (st * st + EPSF));
    float rdel = (float)r * DTH_F;
    float c0   = -mu_k * sL;
    float c1   = -(TWO_PI_F + mu_k) * sL;

    // ---- stage A (float4 stores) ----
    if (tid < V_N) {
        int v   = tid;
        int idx = s * V_N + v;
        float rh = rho[idx];
        float m  = mask[idx];
        t_s[v]   = theta[idx];
        float fv[5];
#pragma unroll
        for (int f = 0; f < 5; f++) fv[f] = feat[idx * 5 + f];
        float ar[32];
#pragma unroll
        for (int p = 0; p < NR; p++) {
            float mr = __ldg(&mu_rho[p * 16]);
            float sr = __ldg(&sigma_rho[p * 16]);
            float d  = rh - mr;
            float rg = ex2f(-(d * d) * (LOG2E_F / (sr * sr + EPSF)));
            float rm = rg * m;
            ar[p * 6] = rm;
#pragma unroll
            for (int f = 0; f < 5; f++) ar[p * 6 + 1 + f] = rm * fv[f];
        }
        ar[30] = 0.0f; ar[31] = 0.0f;
        float4* dst = (float4*)(As + v * 32);
#pragma unroll
        for (int j4 = 0; j4 < 8; j4++) dst[j4] = ((const float4*)ar)[j4];
    } else if (tid < V_N + 8) {
        ((float4*)(As + V_N * 32))[tid - V_N] = make_float4(0.f, 0.f, 0.f, 0.f);
    }
    __syncthreads();

    // ---- main loop ----
    ull acc[16];
#pragma unroll
    for (int j = 0; j < 16; j++) acc[j] = 0ull;

    ulonglong2 qA[4], qB[4];
    {
        const ulonglong2* row0 = (const ulonglong2*)As;
#pragma unroll
        for (int j = 0; j < 4; j++) qA[j] = row0[j];
    }

#define K12_STEP(TV, VV, CUR, NXT)                                            \
    {                                                                         \
        const ulonglong2* rn = (const ulonglong2*)(As + ((VV) + 1) * 32);     \
        _Pragma("unroll")                                                     \
        for (int j = 0; j < 4; j++) NXT[j] = rn[j];                           \
        float tr = (TV) + rdel;                                               \
        float c  = (tr >= TWO_PI_F) ? c1 : c0;                                \
        float x  = fmaf(tr, sL, c);                                           \
        ull tg2  = pack2(ex2f(-x * x));                                       \
        _Pragma("unroll")                                                     \
        for (int j = 0; j < 4; j++) {                                         \
            acc[2 * j + 0] = ffma2(tg2, CUR[j].x, acc[2 * j + 0]);            \
            acc[2 * j + 1] = ffma2(tg2, CUR[j].y, acc[2 * j + 1]);            \
        }                                                                     \
        const ulonglong2* rv = (const ulonglong2*)(As + (VV) * 32) + 4;       \
        _Pragma("unroll")                                                     \
        for (int j = 0; j < 4; j++) {                                         \
            ulonglong2 q = rv[j];                                             \
            acc[8 + 2 * j + 0] = ffma2(tg2, q.x, acc[8 + 2 * j + 0]);         \
            acc[8 + 2 * j + 1] = ffma2(tg2, q.y, acc[8 + 2 * j + 1]);         \
        }                                                                     \
    }

    for (int v = 0; v < V_N; v += 4) {
        float4 th = *(const float4*)&t_s[v];
        K12_STEP(th.x, v,     qA, qB)
        K12_STEP(th.y, v + 1, qB, qA)
        K12_STEP(th.z, v + 2, qA, qB)
        K12_STEP(th.w, v + 3, qB, qA)
    }
#undef K12_STEP

    // ---- normalize + write GDN [s][r][g=p*16+k][8] ----
    float* gbase = d_GDN + (((size_t)s * NROT + r) * G_N + k) * 8;
#pragma unroll
    for (int p = 0; p < NR; p++) {
        float2 q0 = unpack2(acc[p * 3 + 0]);
        float2 q1 = unpack2(acc[p * 3 + 1]);
        float2 q2 = unpack2(acc[p * 3 + 2]);
        float inv = 1.0f / (q0.x + EPSF);
        float4 o0 = make_float4(q0.y * inv, q1.x * inv, q1.y * inv, q2.x * inv);
        float4 o1 = make_float4(q2.y * inv, 0.0f, 0.0f, 0.0f);
        float4* po = (float4*)(gbase + (size_t)p * 128);
        po[0] = o0;
        po[1] = o1;
    }
}

// ---------------------------------------------------------------------------
// k3: grid (S_N, 2) = (s, rotation-half of 8). 320 threads = (rg 0..3, gp);
// each rg handles 2 rotations sharing every W load; FFMA2 accumulation
// (pairs (f0,f1),(f2,f3),(f4,0)). Writes per-half rot-max to d_PMAX.
// ---------------------------------------------------------------------------
__global__ __launch_bounds__(320) void k3_conv(const float* __restrict__ Wc)
{
    __shared__ float Wsh[G_N * G_N];    // 25.6 KB
    __shared__ float gsh[8 * G_N * 8];  // 20.5 KB (reused for reduction)

    int s    = blockIdx.x;
    int half = blockIdx.y;
    int tid  = threadIdx.x;
    int rg   = tid / 80;
    int gp   = tid % 80;

    {
        const float4* wsrc = (const float4*)Wc;
        float4* wdst = (float4*)Wsh;
        for (int i = tid; i < G_N * G_N / 4; i += 320) wdst[i] = wsrc[i];
        const float4* src = (const float4*)(d_GDN + ((size_t)s * 16 + half * 8) * 640);
        float4* dst = (float4*)gsh;
        for (int i = tid; i < 1280; i += 320) dst[i] = src[i];
    }
    __syncthreads();

    const float* ga = &gsh[(rg * 2) * 640];
    const float* gb = ga + 640;
    ull aA0 = 0, aA1 = 0, aA2 = 0, aB0 = 0, aB1 = 0, aB2 = 0;
#pragma unroll 4
    for (int g = 0; g < G_N; g++) {
        ull w2 = pack2(Wsh[g * 80 + gp]);
        ulonglong2 qa = *(const ulonglong2*)&ga[g * 8];   // (f0,f1),(f2,f3)
        ull qa2 = *(const ull*)&ga[g * 8 + 4];            // (f4, 0)
        ulonglong2 qb = *(const ulonglong2*)&gb[g * 8];
        ull qb2 = *(const ull*)&gb[g * 8 + 4];
        aA0 = ffma2(w2, qa.x, aA0); aA1 = ffma2(w2, qa.y, aA1); aA2 = ffma2(w2, qa2, aA2);
        aB0 = ffma2(w2, qb.x, aB0); aB1 = ffma2(w2, qb.y, aB1); aB2 = ffma2(w2, qb2, aB2);
    }
    float2 a01 = unpack2(aA0), a23 = unpack2(aA1), a4 = unpack2(aA2);
    float2 b01 = unpack2(aB0), b23 = unpack2(aB1), b4 = unpack2(aB2);
    float m0 = fmaxf(a01.x, b01.x), m1 = fmaxf(a01.y, b01.y);
    float m2 = fmaxf(a23.x, b23.x), m3 = fmaxf(a23.y, b23.y);
    float m4 = fmaxf(a4.x,  b4.x);

    __syncthreads();
    float* red = gsh;
    red[rg * 400 + 0 * 80 + gp] = m0;
    red[rg * 400 + 1 * 80 + gp] = m1;
    red[rg * 400 + 2 * 80 + gp] = m2;
    red[rg * 400 + 3 * 80 + gp] = m3;
    red[rg * 400 + 4 * 80 + gp] = m4;
    __syncthreads();

    float* pout = d_PMAX + (size_t)half * S_N * 400 + (size_t)s * 400;
    {
        int j = tid;
        float v = fmaxf(fmaxf(red[j], red[400 + j]), fmaxf(red[800 + j], red[1200 + j]));
        pout[j] = v;
        if (tid < 80) {
            int j2 = 320 + tid;
            float v2 = fmaxf(fmaxf(red[j2], red[400 + j2]),
                             fmaxf(red[800 + j2], red[1200 + j2]));
            pout[j2] = v2;
        }
    }
}

// ---------------------------------------------------------------------------
// k45: grid 64, block 320 = (s_local 0..3, g 0..79). fcc with fw staged via
// smem chunks; the LAST block (atomic counter) then computes score + loss.
// out: [0:20480) global_desc, [20480] data_loss, [20481:20609) score
// ---------------------------------------------------------------------------
__global__ __launch_bounds__(320) void k45_fcc_loss(const float* __restrict__ bc,
                                                    const float* __restrict__ fw,
                                                    const float* __restrict__ fb,
                                                    float* __restrict__ out)
{
    __shared__ float fwsh[100 * 80];   // 32 KB chunk
    __shared__ float dsh[4 * 400];
    __shared__ float stats[4];
    __shared__ int   isLast;

    int tid = threadIdx.x;
    int sl  = tid / 80;
    int g   = tid % 80;
    int sb  = blockIdx.x * 4;

    for (int i = tid; i < 4 * 400; i += 320) {
        int s_loc = i / 400, j = i % 400;
        int s = sb + s_loc;
        float v = fmaxf(d_PMAX[(size_t)s * 400 + j],
                        d_PMAX[(size_t)S_N * 400 + (size_t)s * 400 + j]);
        dsh[i] = fmaxf(v + bc[j], 0.0f);
    }

    float acc = 0.0f;
#pragma unroll
    for (int c = 0; c < 4; c++) {
        __syncthreads();
        const float4* src = (const float4*)(fw + (size_t)c * 100 * 80);
        float4* dst = (float4*)fwsh;
        for (int i = tid; i < 2000; i += 320) dst[i] = src[i];
        __syncthreads();

        const float* dr = &dsh[sl * 400 + c * 100];
#pragma unroll 5
        for (int j = 0; j < 100; j++)
            acc = fmaf(dr[j], fwsh[j * 80 + g], acc);
    }

    out[(size_t)(sb + sl) * 80 + g] = fb[g] + acc;

    // ---- completion counter; last block computes the loss ----
    __threadfence();
    if (tid == 0) isLast = (atomicAdd(&d_CTR, 1) == 63);
    __syncthreads();
    if (!isLast) return;

    float* sdist = dsh;   // reuse
    int w    = tid >> 5;  // 10 warps
    int lane = tid & 31;
    const float* gd = out;

    for (int p = w; p < 128; p += 10) {
        int il = p & 63;
        const float *xa, *xb;
        if (p < 64) { xa = gd + (size_t)(64 + il) * 80;  xb = gd + (size_t)il * 80; }
        else        { xa = gd + (size_t)(128 + il) * 80; xb = gd + (size_t)(192 + il) * 80; }
        float sum = 0.0f;
        if (lane < 20) {
            float4 a4 = ((const float4*)xa)[lane];
            float4 b4 = ((const float4*)xb)[lane];
            float dx = a4.x - b4.x, dy = a4.y - b4.y;
            float dz = a4.z - b4.z, dw = a4.w - b4.w;
            sum = dx * dx + dy * dy + dz * dz + dw * dw;
        }
#pragma unroll
        for (int off = 16; off; off >>= 1)
            sum += __shfl_xor_sync(0xffffffffu, sum, off);
        if (lane == 0) { sdist[p] = sum; out[20481 + p] = sum; }
    }
    __syncthreads();

    if (w == 0) {
        float v1 = fmaxf(sdist[lane], 0.0f);
        float v2 = fmaxf(sdist[lane + 32], 0.0f);
        float sum = v1 + v2;
#pragma unroll
        for (int off = 16; off; off >>= 1)
            sum += __shfl_xor_sync(0xffffffffu, sum, off);
        float m = sum * (1.0f / 64.0f);
        float q = (v1 - m) * (v1 - m) + (v2 - m) * (v2 - m);
#pragma unroll
        for (int off = 16; off; off >>= 1)
            q += __shfl_xor_sync(0xffffffffu, q, off);
        if (lane == 0) { stats[0] = m; stats[1] = q; }
    } else if (w == 1) {
        float v1 = fmaxf(10.0f - sdist[64 + lane], 0.0f);
        float v2 = fmaxf(10.0f - sdist[96 + lane], 0.0f);
        float sum = v1 + v2;
#pragma unroll
        for (int off = 16; off; off >>= 1)
            sum += __shfl_xor_sync(0xffffffffu, sum, off);
        float m = sum * (1.0f / 64.0f);
        float q = (v1 - m) * (v1 - m) + (v2 - m) * (v2 - m);
#pragma unroll
        for (int off = 16; off; off >>= 1)
            q += __shfl_xor_sync(0xffffffffu, q, off);
        if (lane == 0) { stats[2] = m; stats[3] = q; }
    }
    __syncthreads();

    if (tid == 0)
        out[20480] = sqrtf(stats[1] / 63.0f) + sqrtf(stats[3] / 63.0f)
                   + stats[0] + stats[2];
}

// ---------------------------------------------------------------------------
extern "C" void kernel_launch(void* const* d_in, const int* in_sizes, int n_in,
                              void* d_out, int out_size)
{
    const float* input_feat  = (const float*)d_in[0];
    const float* rho_coords  = (const float*)d_in[1];
    const float* theta_coord = (const float*)d_in[2];
    const float* mask        = (const float*)d_in[3];
    const float* mu_rho      = (const float*)d_in[4];
    const float* sigma_rho   = (const float*)d_in[5];
    const float* mu_theta    = (const float*)d_in[6];
    const float* sigma_theta = (const float*)d_in[7];
    const float* W_conv      = (const float*)d_in[8];
    const float* b_conv      = (const float*)d_in[9];
    const float* fcc_w       = (const float*)d_in[10];
    const float* fcc_b       = (const float*)d_in[11];
    float* out = (float*)d_out;

    k12<<<S_N, 256>>>(input_feat, rho_coords, theta_coord, mask,
                      mu_rho, sigma_rho, mu_theta, sigma_theta);
    k3_conv<<<dim3(S_N, 2), 320>>>(W_conv);
    k45_fcc_loss<<<S_N / 4, 320>>>(b_conv, fcc_w, fcc_b, out);
}

// round 8
// speedup vs baseline: 1.0005x; 1.0005x over previous
#include <cuda_runtime.h>
#include <math.h>

// Problem constants
#define S_N   256
#define V_N   200
#define F_N   5
#define G_N   80
#define NT    16
#define NR    5
#define NROT  16
#define EPSF  1e-5f

#define TWO_PI_F 6.28318530717958647692f
#define DTH_F    0.39269908169872415481f
#define LOG2E_F  1.44269504088896340736f

typedef unsigned long long ull;

// Scratch
__device__ float d_GDN[(size_t)S_N * NROT * G_N * 8];   // [s][r][g=p*16+k][8]
__device__ float d_PMAX[(size_t)2 * S_N * 400];         // [half][s][f*80+gp]

// ---------------- packed f32x2 helpers ----------------
__device__ __forceinline__ ull ffma2(ull a, ull b, ull c) {
    ull d;
    asm("fma.rn.f32x2 %0, %1, %2, %3;" : "=l"(d) : "l"(a), "l"(b), "l"(c));
    return d;
}
__device__ __forceinline__ ull addf2(ull a, ull b) {
    ull d;
    asm("add.rn.f32x2 %0, %1, %2;" : "=l"(d) : "l"(a), "l"(b));
    return d;
}
__device__ __forceinline__ ull pack2(float x) {
    ull d;
    asm("mov.b64 %0, {%1, %1};" : "=l"(d) : "f"(x));
    return d;
}
__device__ __forceinline__ float2 unpack2(ull v) {
    float2 f;
    asm("mov.b64 {%0, %1}, %2;" : "=f"(f.x), "=f"(f.y) : "l"(v));
    return f;
}
__device__ __forceinline__ float ex2f(float x) {
    float r;
    asm("ex2.approx.f32 %0, %1;" : "=f"(r) : "f"(x));
    return r;
}

// ---------------------------------------------------------------------------
// k12: grid (S_N, 2) = (s, rotation-half). 256 threads = (v-half, r 0..7, k).
// Each thread accumulates its 100-v partial of the 32-wide GEMM row for one
// (r = rhalf*8 + rl, k), with ping-pong LDS.128 prefetch. Halves combined via
// smem (f32x2 adds), then normalize + write GDN. 512 blocks -> 2x occupancy.
// ---------------------------------------------------------------------------
__global__ __launch_bounds__(256) void k12(const float* __restrict__ feat,
                                           const float* __restrict__ rho,
                                           const float* __restrict__ theta,
                                           const float* __restrict__ mask,
                                           const float* __restrict__ mu_rho,
                                           const float* __restrict__ sigma_rho,
                                           const float* __restrict__ mu_theta,
                                           const float* __restrict__ sigma_theta)
{
    __shared__ float As[(V_N + 1) * 32];   // +1 zero pad row for prefetch overrun
    __shared__ float t_s[V_N];

    int s   = blockIdx.x;
    int rh  = blockIdx.y;                  // rotation half
    int tid = threadIdx.x;
    int vh  = tid >> 7;                    // v half
    int l   = tid & 127;
    int r   = (l >> 4) + rh * 8;           // global rotation
    int k   = l & 15;

    // theta-gaussian constants
    float mu_k = __ldg(&mu_theta[k]);
    float st   = __ldg(&sigma_theta[k]);
    float sL   = sqrtf(LOG2E_F / (st * st + EPSF));
    float rdel = (float)r * DTH_F;
    float c0   = -mu_k * sL;
    float c1   = -(TWO_PI_F + mu_k) * sL;

    // ---- stage A (float4 stores), all 200 rows ----
    if (tid < V_N) {
        int v   = tid;
        int idx = s * V_N + v;
        float rhv = rho[idx];
        float m   = mask[idx];
        t_s[v]    = theta[idx];
        float fv[5];
#pragma unroll
        for (int f = 0; f < 5; f++) fv[f] = feat[idx * 5 + f];
        float ar[32];
#pragma unroll
        for (int p = 0; p < NR; p++) {
            float mr = __ldg(&mu_rho[p * 16]);
            float sr = __ldg(&sigma_rho[p * 16]);
            float d  = rhv - mr;
            float rg = ex2f(-(d * d) * (LOG2E_F / (sr * sr + EPSF)));
            float rm = rg * m;
            ar[p * 6] = rm;
#pragma unroll
            for (int f = 0; f < 5; f++) ar[p * 6 + 1 + f] = rm * fv[f];
        }
        ar[30] = 0.0f; ar[31] = 0.0f;
        float4* dst = (float4*)(As + v * 32);
#pragma unroll
        for (int j4 = 0; j4 < 8; j4++) dst[j4] = ((const float4*)ar)[j4];
    } else if (tid < V_N + 8) {
        ((float4*)(As + V_N * 32))[tid - V_N] = make_float4(0.f, 0.f, 0.f, 0.f);
    }
    __syncthreads();

    // ---- main loop: 100 v of this half, ping-pong prefetch ----
    ull acc[16];
#pragma unroll
    for (int j = 0; j < 16; j++) acc[j] = 0ull;

    const int vbase = vh * 100;
    ulonglong2 qA[4], qB[4];
    {
        const ulonglong2* row0 = (const ulonglong2*)(As + vbase * 32);
#pragma unroll
        for (int j = 0; j < 4; j++) qA[j] = row0[j];
    }

#pragma unroll 2
    for (int vo = 0; vo < 100; vo += 2) {
        int v = vbase + vo;
        // --- even: consume qA, prefetch row v+1 into qB ---
        {
            const ulonglong2* rn = (const ulonglong2*)(As + (v + 1) * 32);
#pragma unroll
            for (int j = 0; j < 4; j++) qB[j] = rn[j];
        }
        {
            float tr = t_s[v] + rdel;
            float c  = (tr >= TWO_PI_F) ? c1 : c0;
            float x  = fmaf(tr, sL, c);
            ull tg2  = pack2(ex2f(-x * x));
#pragma unroll
            for (int j = 0; j < 4; j++) {
                acc[2 * j + 0] = ffma2(tg2, qA[j].x, acc[2 * j + 0]);
                acc[2 * j + 1] = ffma2(tg2, qA[j].y, acc[2 * j + 1]);
            }
            const ulonglong2* rv = (const ulonglong2*)(As + v * 32) + 4;
#pragma unroll
            for (int j = 0; j < 4; j++) {
                ulonglong2 q = rv[j];
                acc[8 + 2 * j + 0] = ffma2(tg2, q.x, acc[8 + 2 * j + 0]);
                acc[8 + 2 * j + 1] = ffma2(tg2, q.y, acc[8 + 2 * j + 1]);
            }
        }
        // --- odd: consume qB, prefetch row v+2 into qA (row 200 = zero pad) ---
        {
            const ulonglong2* rn = (const ulonglong2*)(As + (v + 2) * 32);
#pragma unroll
            for (int j = 0; j < 4; j++) qA[j] = rn[j];
        }
        {
            float tr = t_s[v + 1] + rdel;
            float c  = (tr >= TWO_PI_F) ? c1 : c0;
            float x  = fmaf(tr, sL, c);
            ull tg2  = pack2(ex2f(-x * x));
#pragma unroll
            for (int j = 0; j < 4; j++) {
                acc[2 * j + 0] = ffma2(tg2, qB[j].x, acc[2 * j + 0]);
                acc[2 * j + 1] = ffma2(tg2, qB[j].y, acc[2 * j + 1]);
            }
            const ulonglong2* rv = (const ulonglong2*)(As + (v + 1) * 32) + 4;
#pragma unroll
            for (int j = 0; j < 4; j++) {
                ulonglong2 q = rv[j];
                acc[8 + 2 * j + 0] = ffma2(tg2, q.x, acc[8 + 2 * j + 0]);
                acc[8 + 2 * j + 1] = ffma2(tg2, q.y, acc[8 + 2 * j + 1]);
            }
        }
    }

    // ---- combine halves via smem (conflict-free [j*128 + l] layout) ----
    __syncthreads();   // done reading As/t_s
    ull* cbuf = (ull*)As;   // 16 * 128 ull = 16 KB, fits in As region
    if (vh == 1) {
#pragma unroll
        for (int j = 0; j < 16; j++) cbuf[j * 128 + l] = acc[j];
    }
    __syncthreads();
    if (vh == 0) {
#pragma unroll
        for (int j = 0; j < 16; j++) acc[j] = addf2(acc[j], cbuf[j * 128 + l]);

        // normalize + write GDN [s][r][g=p*16+k][8]
        float* gbase = d_GDN + (((size_t)s * NROT + r) * G_N + k) * 8;
#pragma unroll
        for (int p = 0; p < NR; p++) {
            float2 q0 = unpack2(acc[p * 3 + 0]);
            float2 q1 = unpack2(acc[p * 3 + 1]);
            float2 q2 = unpack2(acc[p * 3 + 2]);
            float inv = 1.0f / (q0.x + EPSF);
            float4 o0 = make_float4(q0.y * inv, q1.x * inv, q1.y * inv, q2.x * inv);
            float4 o1 = make_float4(q2.y * inv, 0.0f, 0.0f, 0.0f);
            float4* po = (float4*)(gbase + (size_t)p * 128);
            po[0] = o0;
            po[1] = o1;
        }
    }
}

// ---------------------------------------------------------------------------
// k3: grid (S_N, 2) = (s, rotation-half of 8). 320 threads = (rg 0..3, gp);
// each rg handles 2 rotations sharing every W load. Writes per-half rot-max.
// ---------------------------------------------------------------------------
__global__ __launch_bounds__(320) void k3_conv(const float* __restrict__ Wc)
{
    __shared__ float Wsh[G_N * G_N];    // 25.6 KB
    __shared__ float gsh[8 * G_N * 8];  // 20.5 KB (reused for reduction)

    int s    = blockIdx.x;
    int half = blockIdx.y;
    int tid  = threadIdx.x;
    int rg   = tid / 80;
    int gp   = tid % 80;

    {
        const float4* wsrc = (const float4*)Wc;
        float4* wdst = (float4*)Wsh;
        for (int i = tid; i < G_N * G_N / 4; i += 320) wdst[i] = wsrc[i];
        const float4* src = (const float4*)(d_GDN + ((size_t)s * 16 + half * 8) * 640);
        float4* dst = (float4*)gsh;
        for (int i = tid; i < 1280; i += 320) dst[i] = src[i];
    }
    __syncthreads();

    const float* ga = &gsh[(rg * 2) * 640];
    const float* gb = ga + 640;
    float a0 = 0.f, a1 = 0.f, a2 = 0.f, a3 = 0.f, a4 = 0.f;
    float b0 = 0.f, b1 = 0.f, b2 = 0.f, b3 = 0.f, b4 = 0.f;
#pragma unroll 4
    for (int g = 0; g < G_N; g++) {
        float w   = Wsh[g * 80 + gp];
        float4 xa = *(const float4*)&ga[g * 8];
        float xa4 = ga[g * 8 + 4];
        float4 xb = *(const float4*)&gb[g * 8];
        float xb4 = gb[g * 8 + 4];
        a0 = fmaf(xa.x, w, a0); a1 = fmaf(xa.y, w, a1); a2 = fmaf(xa.z, w, a2);
        a3 = fmaf(xa.w, w, a3); a4 = fmaf(xa4,  w, a4);
        b0 = fmaf(xb.x, w, b0); b1 = fmaf(xb.y, w, b1); b2 = fmaf(xb.z, w, b2);
        b3 = fmaf(xb.w, w, b3); b4 = fmaf(xb4,  w, b4);
    }
    float m0 = fmaxf(a0, b0), m1 = fmaxf(a1, b1), m2 = fmaxf(a2, b2);
    float m3 = fmaxf(a3, b3), m4 = fmaxf(a4, b4);

    __syncthreads();
    float* red = gsh;
    red[rg * 400 + 0 * 80 + gp] = m0;
    red[rg * 400 + 1 * 80 + gp] = m1;
    red[rg * 400 + 2 * 80 + gp] = m2;
    red[rg * 400 + 3 * 80 + gp] = m3;
    red[rg * 400 + 4 * 80 + gp] = m4;
    __syncthreads();

    float* pout = d_PMAX + (size_t)half * S_N * 400 + (size_t)s * 400;
    {
        int j = tid;
        float v = fmaxf(fmaxf(red[j], red[400 + j]), fmaxf(red[800 + j], red[1200 + j]));
        pout[j] = v;
        if (tid < 80) {
            int j2 = 320 + tid;
            float v2 = fmaxf(fmaxf(red[j2], red[400 + j2]),
                             fmaxf(red[800 + j2], red[1200 + j2]));
            pout[j2] = v2;
        }
    }
}

// ---------------------------------------------------------------------------
// k4: grid 64, block 320 = (s_local 0..3, g 0..79). fw staged via smem chunks.
// ---------------------------------------------------------------------------
__global__ __launch_bounds__(320) void k4_fcc(const float* __restrict__ bc,
                                              const float* __restrict__ fw,
                                              const float* __restrict__ fb,
                                              float* __restrict__ out)
{
    __shared__ float fwsh[100 * 80];   // 32 KB chunk
    __shared__ float dsh[4 * 400];

    int tid = threadIdx.x;
    int sl  = tid / 80;
    int g   = tid % 80;
    int sb  = blockIdx.x * 4;

    for (int i = tid; i < 4 * 400; i += 320) {
        int s_loc = i / 400, j = i % 400;
        int s = sb + s_loc;
        float v = fmaxf(d_PMAX[(size_t)s * 400 + j],
                        d_PMAX[(size_t)S_N * 400 + (size_t)s * 400 + j]);
        dsh[i] = fmaxf(v + bc[j], 0.0f);
    }

    float acc = 0.0f;
#pragma unroll
    for (int c = 0; c < 4; c++) {
        __syncthreads();
        const float4* src = (const float4*)(fw + (size_t)c * 100 * 80);
        float4* dst = (float4*)fwsh;
        for (int i = tid; i < 2000; i += 320) dst[i] = src[i];
        __syncthreads();

        const float* dr = &dsh[sl * 400 + c * 100];
#pragma unroll 5
        for (int j = 0; j < 100; j++)
            acc = fmaf(dr[j], fwsh[j * 80 + g], acc);
    }

    out[(size_t)(sb + sl) * 80 + g] = fb[g] + acc;
}

// ---------------------------------------------------------------------------
// k5: distances + score + loss. 1024 threads; warp-per-pair, float4 loads,
// shfl reductions. out: [0:20480) desc, [20480] loss, [20481:20609) score
// ---------------------------------------------------------------------------
__global__ __launch_bounds__(1024) void k5_loss(float* __restrict__ out)
{
    __shared__ float sdist[128];
    __shared__ float stats[4];

    int tid  = threadIdx.x;
    int w    = tid >> 5;
    int lane = tid & 31;
    const float* gd = out;

#pragma unroll
    for (int i = 0; i < 4; i++) {
        int p  = w + 32 * i;     // 0..127
        int il = p & 63;
        const float *xa, *xb;
        if (p < 64) { xa = gd + (size_t)(64 + il) * 80;  xb = gd + (size_t)il * 80; }
        else        { xa = gd + (size_t)(128 + il) * 80; xb = gd + (size_t)(192 + il) * 80; }
        float sum = 0.0f;
        if (lane < 20) {
            float4 a4 = ((const float4*)xa)[lane];
            float4 b4 = ((const float4*)xb)[lane];
            float dx = a4.x - b4.x, dy = a4.y - b4.y;
            float dz = a4.z - b4.z, dw = a4.w - b4.w;
            sum = dx * dx + dy * dy + dz * dz + dw * dw;
        }
#pragma unroll
        for (int off = 16; off; off >>= 1)
            sum += __shfl_xor_sync(0xffffffffu, sum, off);
        if (lane == 0) { sdist[p] = sum; out[20481 + p] = sum; }
    }
    __syncthreads();

    if (w == 0) {
        float v1 = fmaxf(sdist[lane], 0.0f);
        float v2 = fmaxf(sdist[lane + 32], 0.0f);
        float sum = v1 + v2;
#pragma unroll
        for (int off = 16; off; off >>= 1)
            sum += __shfl_xor_sync(0xffffffffu, sum, off);
        float m = sum * (1.0f / 64.0f);
        float q = (v1 - m) * (v1 - m) + (v2 - m) * (v2 - m);
#pragma unroll
        for (int off = 16; off; off >>= 1)
            q += __shfl_xor_sync(0xffffffffu, q, off);
        if (lane == 0) { stats[0] = m; stats[1] = q; }
    } else if (w == 1) {
        float v1 = fmaxf(10.0f - sdist[64 + lane], 0.0f);
        float v2 = fmaxf(10.0f - sdist[96 + lane], 0.0f);
        float sum = v1 + v2;
#pragma unroll
        for (int off = 16; off; off >>= 1)
            sum += __shfl_xor_sync(0xffffffffu, sum, off);
        float m = sum * (1.0f / 64.0f);
        float q = (v1 - m) * (v1 - m) + (v2 - m) * (v2 - m);
#pragma unroll
        for (int off = 16; off; off >>= 1)
            q += __shfl_xor_sync(0xffffffffu, q, off);
        if (lane == 0) { stats[2] = m; stats[3] = q; }
    }
    __syncthreads();

    if (tid == 0)
        out[20480] = sqrtf(stats[1] / 63.0f) + sqrtf(stats[3] / 63.0f)
                   + stats[0] + stats[2];
}

// ---------------------------------------------------------------------------
extern "C" void kernel_launch(void* const* d_in, const int* in_sizes, int n_in,
                              void* d_out, int out_size)
{
    const float* input_feat  = (const float*)d_in[0];
    const float* rho_coords  = (const float*)d_in[1];
    const float* theta_coord = (const float*)d_in[2];
    const float* mask        = (const float*)d_in[3];
    const float* mu_rho      = (const float*)d_in[4];
    const float* sigma_rho   = (const float*)d_in[5];
    const float* mu_theta    = (const float*)d_in[6];
    const float* sigma_theta = (const float*)d_in[7];
    const float* W_conv      = (const float*)d_in[8];
    const float* b_conv      = (const float*)d_in[9];
    const float* fcc_w       = (const float*)d_in[10];
    const float* fcc_b       = (const float*)d_in[11];
    float* out = (float*)d_out;

    k12<<<dim3(S_N, 2), 256>>>(input_feat, rho_coords, theta_coord, mask,
                               mu_rho, sigma_rho, mu_theta, sigma_theta);
    k3_conv<<<dim3(S_N, 2), 320>>>(W_conv);
    k4_fcc<<<S_N / 4, 320>>>(b_conv, fcc_w, fcc_b, out);
    k5_loss<<<1, 1024>>>(out);
}

// round 9
// speedup vs baseline: 1.0407x; 1.0402x over previous
#include <cuda_runtime.h>
#include <math.h>

// Problem constants
#define S_N   256
#define V_N   200
#define F_N   5
#define G_N   80
#define NT    16
#define NR    5
#define NROT  16
#define EPSF  1e-5f

#define TWO_PI_F 6.28318530717958647692f
#define DTH_F    0.39269908169872415481f
#define LOG2E_F  1.44269504088896340736f

typedef unsigned long long ull;

// Scratch
__device__ float d_GDN[(size_t)S_N * NROT * G_N * 8];   // [s][r][g=p*16+k][8]
__device__ float d_PMAX[(size_t)2 * S_N * 400];         // [half][s][f*80+gp]
__device__ int   d_CTR;                                  // k45 completion counter

// ---------------- packed f32x2 helpers ----------------
__device__ __forceinline__ ull ffma2(ull a, ull b, ull c) {
    ull d;
    asm("fma.rn.f32x2 %0, %1, %2, %3;" : "=l"(d) : "l"(a), "l"(b), "l"(c));
    return d;
}
__device__ __forceinline__ ull addf2(ull a, ull b) {
    ull d;
    asm("add.rn.f32x2 %0, %1, %2;" : "=l"(d) : "l"(a), "l"(b));
    return d;
}
__device__ __forceinline__ ull pack2(float x) {
    ull d;
    asm("mov.b64 %0, {%1, %1};" : "=l"(d) : "f"(x));
    return d;
}
__device__ __forceinline__ float2 unpack2(ull v) {
    float2 f;
    asm("mov.b64 {%0, %1}, %2;" : "=f"(f.x), "=f"(f.y) : "l"(v));
    return f;
}
__device__ __forceinline__ float ex2f(float x) {
    float r;
    asm("ex2.approx.f32 %0, %1;" : "=f"(r) : "f"(x));
    return r;
}

// Normalize 5 (den,f0..f4) pair-groups and write one GDN row.
__device__ __forceinline__ void gdn_epilogue(const ull* acc, float* gbase)
{
#pragma unroll
    for (int p = 0; p < NR; p++) {
        float2 q0 = unpack2(acc[p * 3 + 0]);
        float2 q1 = unpack2(acc[p * 3 + 1]);
        float2 q2 = unpack2(acc[p * 3 + 2]);
        float inv = 1.0f / (q0.x + EPSF);
        float4 o0 = make_float4(q0.y * inv, q1.x * inv, q1.y * inv, q2.x * inv);
        float4 o1 = make_float4(q2.y * inv, 0.0f, 0.0f, 0.0f);
        float4* po = (float4*)(gbase + (size_t)p * 128);
        po[0] = o0;
        po[1] = o1;
    }
}

// ---------------------------------------------------------------------------
// k12: one block per s, 256 threads = (v-half 0/1) x (r2 0..7, k 0..15).
// Each thread accumulates TWO rotations (r2, r2+8) over its half's 100 v,
// sharing every A-row load across both rotations (halves smem crossbar work).
// Ping-pong LDS.128 prefetch; halves combined via smem in 2 phases (16 KB).
// ---------------------------------------------------------------------------
__global__ __launch_bounds__(256, 2)
void k12(const float* __restrict__ feat,
         const float* __restrict__ rho,
         const float* __restrict__ theta,
         const float* __restrict__ mask,
         const float* __restrict__ mu_rho,
         const float* __restrict__ sigma_rho,
         const float* __restrict__ mu_theta,
         const float* __restrict__ sigma_theta)
{
    __shared__ float As[(V_N + 2) * 32];   // +2 zero pad rows for prefetch overrun
    __shared__ float t_s[V_N];

    int s   = blockIdx.x;
    int tid = threadIdx.x;
    int vh  = tid >> 7;                    // v half
    int l   = tid & 127;
    int r2  = l >> 4;                      // 0..7
    int k   = l & 15;

    if (s == 0 && tid == 0) d_CTR = 0;     // reset k45 counter (stream-ordered)

    // theta-gaussian constants (one k, two rotations)
    float mu_k  = __ldg(&mu_theta[k]);
    float st    = __ldg(&sigma_theta[k]);
    float sL    = sqrtf(LOG2E_F / (st * st + EPSF));
    float rdelA = (float)r2 * DTH_F;
    float rdelB = (float)(r2 + 8) * DTH_F;
    float c0    = -mu_k * sL;
    float c1    = -(TWO_PI_F + mu_k) * sL;

    // ---- stage A, all 200 rows (float4 stores) ----
    if (tid < V_N) {
        int v   = tid;
        int idx = s * V_N + v;
        float rhv = rho[idx];
        float m   = mask[idx];
        t_s[v]    = theta[idx];
        float fv[5];
#pragma unroll
        for (int f = 0; f < 5; f++) fv[f] = feat[idx * 5 + f];
        float ar[32];
#pragma unroll
        for (int p = 0; p < NR; p++) {
            float mr = __ldg(&mu_rho[p * 16]);
            float sr = __ldg(&sigma_rho[p * 16]);
            float d  = rhv - mr;
            float rg = ex2f(-(d * d) * (LOG2E_F / (sr * sr + EPSF)));
            float rm = rg * m;
            ar[p * 6] = rm;
#pragma unroll
            for (int f = 0; f < 5; f++) ar[p * 6 + 1 + f] = rm * fv[f];
        }
        ar[30] = 0.0f; ar[31] = 0.0f;
        float4* dst = (float4*)(As + v * 32);
#pragma unroll
        for (int j4 = 0; j4 < 8; j4++) dst[j4] = ((const float4*)ar)[j4];
    } else if (tid < V_N + 16) {
        // zero pad rows 200, 201
        ((float4*)(As + V_N * 32))[tid - V_N] = make_float4(0.f, 0.f, 0.f, 0.f);
    }
    __syncthreads();

    // ---- main loop: 100 v of this half, 2 rotations per thread ----
    ull accA[16], accB[16];
#pragma unroll
    for (int j = 0; j < 16; j++) { accA[j] = 0ull; accB[j] = 0ull; }

    const int vbase = vh * 100;
    ulonglong2 qA[4], qB[4];
    {
        const ulonglong2* row0 = (const ulonglong2*)(As + vbase * 32);
#pragma unroll
        for (int j = 0; j < 4; j++) qA[j] = row0[j];
    }

#pragma unroll 2
    for (int vo = 0; vo < 100; vo += 2) {
        int v = vbase + vo;
        // --- even: consume qA, prefetch row v+1 into qB ---
        {
            const ulonglong2* rn = (const ulonglong2*)(As + (v + 1) * 32);
#pragma unroll
            for (int j = 0; j < 4; j++) qB[j] = rn[j];
        }
        {
            float tv  = t_s[v];
            float trA = tv + rdelA;
            float cA  = (trA >= TWO_PI_F) ? c1 : c0;
            float xA  = fmaf(trA, sL, cA);
            ull tgA   = pack2(ex2f(-xA * xA));
            float trB = tv + rdelB;
            float cB  = (trB >= TWO_PI_F) ? c1 : c0;
            float xB  = fmaf(trB, sL, cB);
            ull tgB   = pack2(ex2f(-xB * xB));
#pragma unroll
            for (int j = 0; j < 4; j++) {
                accA[2 * j + 0] = ffma2(tgA, qA[j].x, accA[2 * j + 0]);
                accA[2 * j + 1] = ffma2(tgA, qA[j].y, accA[2 * j + 1]);
                accB[2 * j + 0] = ffma2(tgB, qA[j].x, accB[2 * j + 0]);
                accB[2 * j + 1] = ffma2(tgB, qA[j].y, accB[2 * j + 1]);
            }
            const ulonglong2* rv = (const ulonglong2*)(As + v * 32) + 4;
#pragma unroll
            for (int j = 0; j < 4; j++) {
                ulonglong2 q = rv[j];
                accA[8 + 2 * j + 0] = ffma2(tgA, q.x, accA[8 + 2 * j + 0]);
                accA[8 + 2 * j + 1] = ffma2(tgA, q.y, accA[8 + 2 * j + 1]);
                accB[8 + 2 * j + 0] = ffma2(tgB, q.x, accB[8 + 2 * j + 0]);
                accB[8 + 2 * j + 1] = ffma2(tgB, q.y, accB[8 + 2 * j + 1]);
            }
        }
        // --- odd: consume qB, prefetch row v+2 into qA ---
        {
            const ulonglong2* rn = (const ulonglong2*)(As + (v + 2) * 32);
#pragma unroll
            for (int j = 0; j < 4; j++) qA[j] = rn[j];
        }
        {
            float tv  = t_s[v + 1];
            float trA = tv + rdelA;
            float cA  = (trA >= TWO_PI_F) ? c1 : c0;
            float xA  = fmaf(trA, sL, cA);
            ull tgA   = pack2(ex2f(-xA * xA));
            float trB = tv + rdelB;
            float cB  = (trB >= TWO_PI_F) ? c1 : c0;
            float xB  = fmaf(trB, sL, cB);
            ull tgB   = pack2(ex2f(-xB * xB));
#pragma unroll
            for (int j = 0; j < 4; j++) {
                accA[2 * j + 0] = ffma2(tgA, qB[j].x, accA[2 * j + 0]);
                accA[2 * j + 1] = ffma2(tgA, qB[j].y, accA[2 * j + 1]);
                accB[2 * j + 0] = ffma2(tgB, qB[j].x, accB[2 * j + 0]);
                accB[2 * j + 1] = ffma2(tgB, qB[j].y, accB[2 * j + 1]);
            }
            const ulonglong2* rv = (const ulonglong2*)(As + (v + 1) * 32) + 4;
#pragma unroll
            for (int j = 0; j < 4; j++) {
                ulonglong2 q = rv[j];
                accA[8 + 2 * j + 0] = ffma2(tgA, q.x, accA[8 + 2 * j + 0]);
                accA[8 + 2 * j + 1] = ffma2(tgA, q.y, accA[8 + 2 * j + 1]);
                accB[8 + 2 * j + 0] = ffma2(tgB, q.x, accB[8 + 2 * j + 0]);
                accB[8 + 2 * j + 1] = ffma2(tgB, q.y, accB[8 + 2 * j + 1]);
            }
        }
    }

    // ---- combine halves via smem, two 16 KB phases (reuse As) ----
    ull* cbuf = (ull*)As;   // 16 * 128 ull = 16 KB
    __syncthreads();        // done reading As/t_s
    if (vh == 1) {
#pragma unroll
        for (int j = 0; j < 16; j++) cbuf[j * 128 + l] = accA[j];
    }
    __syncthreads();
    if (vh == 0) {
#pragma unroll
        for (int j = 0; j < 16; j++) accA[j] = addf2(accA[j], cbuf[j * 128 + l]);
        gdn_epilogue(accA, d_GDN + (((size_t)s * NROT + r2) * G_N + k) * 8);
    }
    __syncthreads();
    if (vh == 1) {
#pragma unroll
        for (int j = 0; j < 16; j++) cbuf[j * 128 + l] = accB[j];
    }
    __syncthreads();
    if (vh == 0) {
#pragma unroll
        for (int j = 0; j < 16; j++) accB[j] = addf2(accB[j], cbuf[j * 128 + l]);
        gdn_epilogue(accB, d_GDN + (((size_t)s * NROT + r2 + 8) * G_N + k) * 8);
    }
}

// ---------------------------------------------------------------------------
// k3: grid (S_N, 2) = (s, rotation-half of 8). 320 threads = (rg 0..3, gp);
// each rg handles 2 rotations sharing every W load. Writes per-half rot-max.
// ---------------------------------------------------------------------------
__global__ __launch_bounds__(320) void k3_conv(const float* __restrict__ Wc)
{
    __shared__ float Wsh[G_N * G_N];    // 25.6 KB
    __shared__ float gsh[8 * G_N * 8];  // 20.5 KB (reused for reduction)

    int s    = blockIdx.x;
    int half = blockIdx.y;
    int tid  = threadIdx.x;
    int rg   = tid / 80;
    int gp   = tid % 80;

    {
        const float4* wsrc = (const float4*)Wc;
        float4* wdst = (float4*)Wsh;
        for (int i = tid; i < G_N * G_N / 4; i += 320) wdst[i] = wsrc[i];
        const float4* src = (const float4*)(d_GDN + ((size_t)s * 16 + half * 8) * 640);
        float4* dst = (float4*)gsh;
        for (int i = tid; i < 1280; i += 320) dst[i] = src[i];
    }
    __syncthreads();

    const float* ga = &gsh[(rg * 2) * 640];
    const float* gb = ga + 640;
    float a0 = 0.f, a1 = 0.f, a2 = 0.f, a3 = 0.f, a4 = 0.f;
    float b0 = 0.f, b1 = 0.f, b2 = 0.f, b3 = 0.f, b4 = 0.f;
#pragma unroll 4
    for (int g = 0; g < G_N; g++) {
        float w   = Wsh[g * 80 + gp];
        float4 xa = *(const float4*)&ga[g * 8];
        float xa4 = ga[g * 8 + 4];
        float4 xb = *(const float4*)&gb[g * 8];
        float xb4 = gb[g * 8 + 4];
        a0 = fmaf(xa.x, w, a0); a1 = fmaf(xa.y, w, a1); a2 = fmaf(xa.z, w, a2);
        a3 = fmaf(xa.w, w, a3); a4 = fmaf(xa4,  w, a4);
        b0 = fmaf(xb.x, w, b0); b1 = fmaf(xb.y, w, b1); b2 = fmaf(xb.z, w, b2);
        b3 = fmaf(xb.w, w, b3); b4 = fmaf(xb4,  w, b4);
    }
    float m0 = fmaxf(a0, b0), m1 = fmaxf(a1, b1), m2 = fmaxf(a2, b2);
    float m3 = fmaxf(a3, b3), m4 = fmaxf(a4, b4);

    __syncthreads();
    float* red = gsh;
    red[rg * 400 + 0 * 80 + gp] = m0;
    red[rg * 400 + 1 * 80 + gp] = m1;
    red[rg * 400 + 2 * 80 + gp] = m2;
    red[rg * 400 + 3 * 80 + gp] = m3;
    red[rg * 400 + 4 * 80 + gp] = m4;
    __syncthreads();

    float* pout = d_PMAX + (size_t)half * S_N * 400 + (size_t)s * 400;
    {
        int j = tid;
        float v = fmaxf(fmaxf(red[j], red[400 + j]), fmaxf(red[800 + j], red[1200 + j]));
        pout[j] = v;
        if (tid < 80) {
            int j2 = 320 + tid;
            float v2 = fmaxf(fmaxf(red[j2], red[400 + j2]),
                             fmaxf(red[800 + j2], red[1200 + j2]));
            pout[j2] = v2;
        }
    }
}

// ---------------------------------------------------------------------------
// k45: grid 64, block 320 = (s_local 0..3, g 0..79). fcc with fw staged via
// smem chunks; the LAST block (atomic counter) computes score + loss.
// out: [0:20480) global_desc, [20480] data_loss, [20481:20609) score
// ---------------------------------------------------------------------------
__global__ __launch_bounds__(320) void k45_fcc_loss(const float* __restrict__ bc,
                                                    const float* __restrict__ fw,
                                                    const float* __restrict__ fb,
                                                    float* __restrict__ out)
{
    __shared__ float fwsh[100 * 80];   // 32 KB chunk
    __shared__ float dsh[4 * 400];
    __shared__ float stats[4];
    __shared__ int   isLast;

    int tid = threadIdx.x;
    int sl  = tid / 80;
    int g   = tid % 80;
    int sb  = blockIdx.x * 4;

    for (int i = tid; i < 4 * 400; i += 320) {
        int s_loc = i / 400, j = i % 400;
        int s = sb + s_loc;
        float v = fmaxf(d_PMAX[(size_t)s * 400 + j],
                        d_PMAX[(size_t)S_N * 400 + (size_t)s * 400 + j]);
        dsh[i] = fmaxf(v + bc[j], 0.0f);
    }

    float acc = 0.0f;
#pragma unroll
    for (int c = 0; c < 4; c++) {
        __syncthreads();
        const float4* src = (const float4*)(fw + (size_t)c * 100 * 80);
        float4* dst = (float4*)fwsh;
        for (int i = tid; i < 2000; i += 320) dst[i] = src[i];
        __syncthreads();

        const float* dr = &dsh[sl * 400 + c * 100];
#pragma unroll 5
        for (int j = 0; j < 100; j++)
            acc = fmaf(dr[j], fwsh[j * 80 + g], acc);
    }

    out[(size_t)(sb + sl) * 80 + g] = fb[g] + acc;

    // ---- completion counter; last block computes the loss ----
    __threadfence();
    if (tid == 0) isLast = (atomicAdd(&d_CTR, 1) == 63);
    __syncthreads();
    if (!isLast) return;

    float* sdist = dsh;   // reuse
    int w    = tid >> 5;  // 10 warps
    int lane = tid & 31;
    const float* gd = out;

    for (int p = w; p < 128; p += 10) {
        int il = p & 63;
        const float *xa, *xb;
        if (p < 64) { xa = gd + (size_t)(64 + il) * 80;  xb = gd + (size_t)il * 80; }
        else        { xa = gd + (size_t)(128 + il) * 80; xb = gd + (size_t)(192 + il) * 80; }
        float sum = 0.0f;
        if (lane < 20) {
            float4 a4 = ((const float4*)xa)[lane];
            float4 b4 = ((const float4*)xb)[lane];
            float dx = a4.x - b4.x, dy = a4.y - b4.y;
            float dz = a4.z - b4.z, dw = a4.w - b4.w;
            sum = dx * dx + dy * dy + dz * dz + dw * dw;
        }
#pragma unroll
        for (int off = 16; off; off >>= 1)
            sum += __shfl_xor_sync(0xffffffffu, sum, off);
        if (lane == 0) { sdist[p] = sum; out[20481 + p] = sum; }
    }
    __syncthreads();

    if (w == 0) {
        float v1 = fmaxf(sdist[lane], 0.0f);
        float v2 = fmaxf(sdist[lane + 32], 0.0f);
        float sum = v1 + v2;
#pragma unroll
        for (int off = 16; off; off >>= 1)
            sum += __shfl_xor_sync(0xffffffffu, sum, off);
        float m = sum * (1.0f / 64.0f);
        float q = (v1 - m) * (v1 - m) + (v2 - m) * (v2 - m);
#pragma unroll
        for (int off = 16; off; off >>= 1)
            q += __shfl_xor_sync(0xffffffffu, q, off);
        if (lane == 0) { stats[0] = m; stats[1] = q; }
    } else if (w == 1) {
        float v1 = fmaxf(10.0f - sdist[64 + lane], 0.0f);
        float v2 = fmaxf(10.0f - sdist[96 + lane], 0.0f);
        float sum = v1 + v2;
#pragma unroll
        for (int off = 16; off; off >>= 1)
            sum += __shfl_xor_sync(0xffffffffu, sum, off);
        float m = sum * (1.0f / 64.0f);
        float q = (v1 - m) * (v1 - m) + (v2 - m) * (v2 - m);
#pragma unroll
        for (int off = 16; off; off >>= 1)
            q += __shfl_xor_sync(0xffffffffu, q, off);
        if (lane == 0) { stats[2] = m; stats[3] = q; }
    }
    __syncthreads();

    if (tid == 0)
        out[20480] = sqrtf(stats[1] / 63.0f) + sqrtf(stats[3] / 63.0f)
                   + stats[0] + stats[2];
}

// ---------------------------------------------------------------------------
extern "C" void kernel_launch(void* const* d_in, const int* in_sizes, int n_in,
                              void* d_out, int out_size)
{
    const float* input_feat  = (const float*)d_in[0];
    const float* rho_coords  = (const float*)d_in[1];
    const float* theta_coord = (const float*)d_in[2];
    const float* mask        = (const float*)d_in[3];
    const float* mu_rho      = (const float*)d_in[4];
    const float* sigma_rho   = (const float*)d_in[5];
    const float* mu_theta    = (const float*)d_in[6];
    const float* sigma_theta = (const float*)d_in[7];
    const float* W_conv      = (const float*)d_in[8];
    const float* b_conv      = (const float*)d_in[9];
    const float* fcc_w       = (const float*)d_in[10];
    const float* fcc_b       = (const float*)d_in[11];
    float* out = (float*)d_out;

    k12<<<S_N, 256>>>(input_feat, rho_coords, theta_coord, mask,
                      mu_rho, sigma_rho, mu_theta, sigma_theta);
    k3_conv<<<dim3(S_N, 2), 320>>>(W_conv);
    k45_fcc_loss<<<S_N / 4, 320>>>(b_conv, fcc_w, fcc_b, out);
}

// round 10
// speedup vs baseline: 1.0956x; 1.0528x over previous
#include <cuda_runtime.h>
#include <math.h>

// Problem constants
#define S_N   256
#define V_N   200
#define F_N   5
#define G_N   80
#define NT    16
#define NR    5
#define NROT  16
#define EPSF  1e-5f

#define TWO_PI_F 6.28318530717958647692f
#define DTH_F    0.39269908169872415481f
#define LOG2E_F  1.44269504088896340736f

typedef unsigned long long ull;

// Scratch
__device__ float d_GDN[(size_t)S_N * NROT * G_N * 8];   // [s][r][g=p*16+k][8]
__device__ float d_PMAX[(size_t)2 * S_N * 400];         // [half][s][f*80+gp]

// ---------------- packed f32x2 helpers ----------------
__device__ __forceinline__ ull ffma2(ull a, ull b, ull c) {
    ull d;
    asm("fma.rn.f32x2 %0, %1, %2, %3;" : "=l"(d) : "l"(a), "l"(b), "l"(c));
    return d;
}
__device__ __forceinline__ ull addf2(ull a, ull b) {
    ull d;
    asm("add.rn.f32x2 %0, %1, %2;" : "=l"(d) : "l"(a), "l"(b));
    return d;
}
__device__ __forceinline__ ull pack2(float x) {
    ull d;
    asm("mov.b64 %0, {%1, %1};" : "=l"(d) : "f"(x));
    return d;
}
__device__ __forceinline__ float2 unpack2(ull v) {
    float2 f;
    asm("mov.b64 {%0, %1}, %2;" : "=f"(f.x), "=f"(f.y) : "l"(v));
    return f;
}
__device__ __forceinline__ float ex2f(float x) {
    float r;
    asm("ex2.approx.f32 %0, %1;" : "=f"(r) : "f"(x));
    return r;
}

// Normalize 5 (den,f0..f4) pair-groups and write one GDN row.
__device__ __forceinline__ void gdn_epilogue(const ull* acc, float* gbase)
{
#pragma unroll
    for (int p = 0; p < NR; p++) {
        float2 q0 = unpack2(acc[p * 3 + 0]);
        float2 q1 = unpack2(acc[p * 3 + 1]);
        float2 q2 = unpack2(acc[p * 3 + 2]);
        float inv = 1.0f / (q0.x + EPSF);
        float4 o0 = make_float4(q0.y * inv, q1.x * inv, q1.y * inv, q2.x * inv);
        float4 o1 = make_float4(q2.y * inv, 0.0f, 0.0f, 0.0f);
        float4* po = (float4*)(gbase + (size_t)p * 128);
        po[0] = o0;
        po[1] = o1;
    }
}

// ---------------------------------------------------------------------------
// k12: one block per s, 256 threads = (v-half 0/1) x (r2 0..7, k 0..15).
// Each thread accumulates TWO rotations (r2, r2+8) over its half's 100 v,
// sharing every A-row load across both rotations. Ping-pong LDS.128 prefetch;
// halves combined via smem in 2 phases.
// ---------------------------------------------------------------------------
__global__ __launch_bounds__(256, 2)
void k12(const float* __restrict__ feat,
         const float* __restrict__ rho,
         const float* __restrict__ theta,
         const float* __restrict__ mask,
         const float* __restrict__ mu_rho,
         const float* __restrict__ sigma_rho,
         const float* __restrict__ mu_theta,
         const float* __restrict__ sigma_theta)
{
    __shared__ float As[(V_N + 2) * 32];   // +2 zero pad rows for prefetch overrun
    __shared__ float t_s[V_N];

    int s   = blockIdx.x;
    int tid = threadIdx.x;
    int vh  = tid >> 7;                    // v half
    int l   = tid & 127;
    int r2  = l >> 4;                      // 0..7
    int k   = l & 15;

    // theta-gaussian constants (one k, two rotations)
    float mu_k  = __ldg(&mu_theta[k]);
    float st    = __ldg(&sigma_theta[k]);
    float sL    = sqrtf(LOG2E_F / (st * st + EPSF));
    float rdelA = (float)r2 * DTH_F;
    float rdelB = (float)(r2 + 8) * DTH_F;
    float c0    = -mu_k * sL;
    float c1    = -(TWO_PI_F + mu_k) * sL;

    // ---- stage A, all 200 rows (float4 stores) ----
    if (tid < V_N) {
        int v   = tid;
        int idx = s * V_N + v;
        float rhv = rho[idx];
        float m   = mask[idx];
        t_s[v]    = theta[idx];
        float fv[5];
#pragma unroll
        for (int f = 0; f < 5; f++) fv[f] = feat[idx * 5 + f];
        float ar[32];
#pragma unroll
        for (int p = 0; p < NR; p++) {
            float mr = __ldg(&mu_rho[p * 16]);
            float sr = __ldg(&sigma_rho[p * 16]);
            float d  = rhv - mr;
            float rg = ex2f(-(d * d) * (LOG2E_F / (sr * sr + EPSF)));
            float rm = rg * m;
            ar[p * 6] = rm;
#pragma unroll
            for (int f = 0; f < 5; f++) ar[p * 6 + 1 + f] = rm * fv[f];
        }
        ar[30] = 0.0f; ar[31] = 0.0f;
        float4* dst = (float4*)(As + v * 32);
#pragma unroll
        for (int j4 = 0; j4 < 8; j4++) dst[j4] = ((const float4*)ar)[j4];
    } else if (tid < V_N + 16) {
        ((float4*)(As + V_N * 32))[tid - V_N] = make_float4(0.f, 0.f, 0.f, 0.f);
    }
    __syncthreads();

    // ---- main loop: 100 v of this half, 2 rotations per thread ----
    ull accA[16], accB[16];
#pragma unroll
    for (int j = 0; j < 16; j++) { accA[j] = 0ull; accB[j] = 0ull; }

    const int vbase = vh * 100;
    ulonglong2 qA[4], qB[4];
    {
        const ulonglong2* row0 = (const ulonglong2*)(As + vbase * 32);
#pragma unroll
        for (int j = 0; j < 4; j++) qA[j] = row0[j];
    }

#pragma unroll 2
    for (int vo = 0; vo < 100; vo += 2) {
        int v = vbase + vo;
        // --- even: consume qA, prefetch row v+1 into qB ---
        {
            const ulonglong2* rn = (const ulonglong2*)(As + (v + 1) * 32);
#pragma unroll
            for (int j = 0; j < 4; j++) qB[j] = rn[j];
        }
        {
            float tv  = t_s[v];
            float trA = tv + rdelA;
            float cA  = (trA >= TWO_PI_F) ? c1 : c0;
            float xA  = fmaf(trA, sL, cA);
            ull tgA   = pack2(ex2f(-xA * xA));
            float trB = tv + rdelB;
            float cB  = (trB >= TWO_PI_F) ? c1 : c0;
            float xB  = fmaf(trB, sL, cB);
            ull tgB   = pack2(ex2f(-xB * xB));
#pragma unroll
            for (int j = 0; j < 4; j++) {
                accA[2 * j + 0] = ffma2(tgA, qA[j].x, accA[2 * j + 0]);
                accA[2 * j + 1] = ffma2(tgA, qA[j].y, accA[2 * j + 1]);
                accB[2 * j + 0] = ffma2(tgB, qA[j].x, accB[2 * j + 0]);
                accB[2 * j + 1] = ffma2(tgB, qA[j].y, accB[2 * j + 1]);
            }
            const ulonglong2* rv = (const ulonglong2*)(As + v * 32) + 4;
#pragma unroll
            for (int j = 0; j < 4; j++) {
                ulonglong2 q = rv[j];
                accA[8 + 2 * j + 0] = ffma2(tgA, q.x, accA[8 + 2 * j + 0]);
                accA[8 + 2 * j + 1] = ffma2(tgA, q.y, accA[8 + 2 * j + 1]);
                accB[8 + 2 * j + 0] = ffma2(tgB, q.x, accB[8 + 2 * j + 0]);
                accB[8 + 2 * j + 1] = ffma2(tgB, q.y, accB[8 + 2 * j + 1]);
            }
        }
        // --- odd: consume qB, prefetch row v+2 into qA ---
        {
            const ulonglong2* rn = (const ulonglong2*)(As + (v + 2) * 32);
#pragma unroll
            for (int j = 0; j < 4; j++) qA[j] = rn[j];
        }
        {
            float tv  = t_s[v + 1];
            float trA = tv + rdelA;
            float cA  = (trA >= TWO_PI_F) ? c1 : c0;
            float xA  = fmaf(trA, sL, cA);
            ull tgA   = pack2(ex2f(-xA * xA));
            float trB = tv + rdelB;
            float cB  = (trB >= TWO_PI_F) ? c1 : c0;
            float xB  = fmaf(trB, sL, cB);
            ull tgB   = pack2(ex2f(-xB * xB));
#pragma unroll
            for (int j = 0; j < 4; j++) {
                accA[2 * j + 0] = ffma2(tgA, qB[j].x, accA[2 * j + 0]);
                accA[2 * j + 1] = ffma2(tgA, qB[j].y, accA[2 * j + 1]);
                accB[2 * j + 0] = ffma2(tgB, qB[j].x, accB[2 * j + 0]);
                accB[2 * j + 1] = ffma2(tgB, qB[j].y, accB[2 * j + 1]);
            }
            const ulonglong2* rv = (const ulonglong2*)(As + (v + 1) * 32) + 4;
#pragma unroll
            for (int j = 0; j < 4; j++) {
                ulonglong2 q = rv[j];
                accA[8 + 2 * j + 0] = ffma2(tgA, q.x, accA[8 + 2 * j + 0]);
                accA[8 + 2 * j + 1] = ffma2(tgA, q.y, accA[8 + 2 * j + 1]);
                accB[8 + 2 * j + 0] = ffma2(tgB, q.x, accB[8 + 2 * j + 0]);
                accB[8 + 2 * j + 1] = ffma2(tgB, q.y, accB[8 + 2 * j + 1]);
            }
        }
    }

    // ---- combine halves via smem, two 16 KB phases (reuse As) ----
    ull* cbuf = (ull*)As;   // 16 * 128 ull = 16 KB
    __syncthreads();        // done reading As/t_s
    if (vh == 1) {
#pragma unroll
        for (int j = 0; j < 16; j++) cbuf[j * 128 + l] = accA[j];
    }
    __syncthreads();
    if (vh == 0) {
#pragma unroll
        for (int j = 0; j < 16; j++) accA[j] = addf2(accA[j], cbuf[j * 128 + l]);
        gdn_epilogue(accA, d_GDN + (((size_t)s * NROT + r2) * G_N + k) * 8);
    }
    __syncthreads();
    if (vh == 1) {
#pragma unroll
        for (int j = 0; j < 16; j++) cbuf[j * 128 + l] = accB[j];
    }
    __syncthreads();
    if (vh == 0) {
#pragma unroll
        for (int j = 0; j < 16; j++) accB[j] = addf2(accB[j], cbuf[j * 128 + l]);
        gdn_epilogue(accB, d_GDN + (((size_t)s * NROT + r2 + 8) * G_N + k) * 8);
    }
}

// ---------------------------------------------------------------------------
// k3: grid (S_N, 2) = (s, rotation-half of 8). 320 threads = (rg 0..3, gp);
// each rg handles 2 rotations sharing every W load. Writes per-half rot-max.
// ---------------------------------------------------------------------------
__global__ __launch_bounds__(320) void k3_conv(const float* __restrict__ Wc)
{
    __shared__ float Wsh[G_N * G_N];    // 25.6 KB
    __shared__ float gsh[8 * G_N * 8];  // 20.5 KB (reused for reduction)

    int s    = blockIdx.x;
    int half = blockIdx.y;
    int tid  = threadIdx.x;
    int rg   = tid / 80;
    int gp   = tid % 80;

    {
        const float4* wsrc = (const float4*)Wc;
        float4* wdst = (float4*)Wsh;
        for (int i = tid; i < G_N * G_N / 4; i += 320) wdst[i] = wsrc[i];
        const float4* src = (const float4*)(d_GDN + ((size_t)s * 16 + half * 8) * 640);
        float4* dst = (float4*)gsh;
        for (int i = tid; i < 1280; i += 320) dst[i] = src[i];
    }
    __syncthreads();

    const float* ga = &gsh[(rg * 2) * 640];
    const float* gb = ga + 640;
    float a0 = 0.f, a1 = 0.f, a2 = 0.f, a3 = 0.f, a4 = 0.f;
    float b0 = 0.f, b1 = 0.f, b2 = 0.f, b3 = 0.f, b4 = 0.f;
#pragma unroll 4
    for (int g = 0; g < G_N; g++) {
        float w   = Wsh[g * 80 + gp];
        float4 xa = *(const float4*)&ga[g * 8];
        float xa4 = ga[g * 8 + 4];
        float4 xb = *(const float4*)&gb[g * 8];
        float xb4 = gb[g * 8 + 4];
        a0 = fmaf(xa.x, w, a0); a1 = fmaf(xa.y, w, a1); a2 = fmaf(xa.z, w, a2);
        a3 = fmaf(xa.w, w, a3); a4 = fmaf(xa4,  w, a4);
        b0 = fmaf(xb.x, w, b0); b1 = fmaf(xb.y, w, b1); b2 = fmaf(xb.z, w, b2);
        b3 = fmaf(xb.w, w, b3); b4 = fmaf(xb4,  w, b4);
    }
    float m0 = fmaxf(a0, b0), m1 = fmaxf(a1, b1), m2 = fmaxf(a2, b2);
    float m3 = fmaxf(a3, b3), m4 = fmaxf(a4, b4);

    __syncthreads();
    float* red = gsh;
    red[rg * 400 + 0 * 80 + gp] = m0;
    red[rg * 400 + 1 * 80 + gp] = m1;
    red[rg * 400 + 2 * 80 + gp] = m2;
    red[rg * 400 + 3 * 80 + gp] = m3;
    red[rg * 400 + 4 * 80 + gp] = m4;
    __syncthreads();

    float* pout = d_PMAX + (size_t)half * S_N * 400 + (size_t)s * 400;
    {
        int j = tid;
        float v = fmaxf(fmaxf(red[j], red[400 + j]), fmaxf(red[800 + j], red[1200 + j]));
        pout[j] = v;
        if (tid < 80) {
            int j2 = 320 + tid;
            float v2 = fmaxf(fmaxf(red[j2], red[400 + j2]),
                             fmaxf(red[800 + j2], red[1200 + j2]));
            pout[j2] = v2;
        }
    }
}

// ---------------------------------------------------------------------------
// k4: grid 64, block 320 = (s_local 0..3, g 0..79). fw staged via smem chunks.
// ---------------------------------------------------------------------------
__global__ __launch_bounds__(320) void k4_fcc(const float* __restrict__ bc,
                                              const float* __restrict__ fw,
                                              const float* __restrict__ fb,
                                              float* __restrict__ out)
{
    __shared__ float fwsh[100 * 80];   // 32 KB chunk
    __shared__ float dsh[4 * 400];

    int tid = threadIdx.x;
    int sl  = tid / 80;
    int g   = tid % 80;
    int sb  = blockIdx.x * 4;

    for (int i = tid; i < 4 * 400; i += 320) {
        int s_loc = i / 400, j = i % 400;
        int s = sb + s_loc;
        float v = fmaxf(d_PMAX[(size_t)s * 400 + j],
                        d_PMAX[(size_t)S_N * 400 + (size_t)s * 400 + j]);
        dsh[i] = fmaxf(v + bc[j], 0.0f);
    }

    float acc = 0.0f;
#pragma unroll
    for (int c = 0; c < 4; c++) {
        __syncthreads();
        const float4* src = (const float4*)(fw + (size_t)c * 100 * 80);
        float4* dst = (float4*)fwsh;
        for (int i = tid; i < 2000; i += 320) dst[i] = src[i];
        __syncthreads();

        const float* dr = &dsh[sl * 400 + c * 100];
#pragma unroll 5
        for (int j = 0; j < 100; j++)
            acc = fmaf(dr[j], fwsh[j * 80 + g], acc);
    }

    out[(size_t)(sb + sl) * 80 + g] = fb[g] + acc;
}

// ---------------------------------------------------------------------------
// k5: distances + score + loss. 1024 threads; warp-per-pair, float4 loads,
// shfl reductions. out: [0:20480) desc, [20480] loss, [20481:20609) score
// ---------------------------------------------------------------------------
__global__ __launch_bounds__(1024) void k5_loss(float* __restrict__ out)
{
    __shared__ float sdist[128];
    __shared__ float stats[4];

    int tid  = threadIdx.x;
    int w    = tid >> 5;
    int lane = tid & 31;
    const float* gd = out;

#pragma unroll
    for (int i = 0; i < 4; i++) {
        int p  = w + 32 * i;     // 0..127
        int il = p & 63;
        const float *xa, *xb;
        if (p < 64) { xa = gd + (size_t)(64 + il) * 80;  xb = gd + (size_t)il * 80; }
        else        { xa = gd + (size_t)(128 + il) * 80; xb = gd + (size_t)(192 + il) * 80; }
        float sum = 0.0f;
        if (lane < 20) {
            float4 a4 = ((const float4*)xa)[lane];
            float4 b4 = ((const float4*)xb)[lane];
            float dx = a4.x - b4.x, dy = a4.y - b4.y;
            float dz = a4.z - b4.z, dw = a4.w - b4.w;
            sum = dx * dx + dy * dy + dz * dz + dw * dw;
        }
#pragma unroll
        for (int off = 16; off; off >>= 1)
            sum += __shfl_xor_sync(0xffffffffu, sum, off);
        if (lane == 0) { sdist[p] = sum; out[20481 + p] = sum; }
    }
    __syncthreads();

    if (w == 0) {
        float v1 = fmaxf(sdist[lane], 0.0f);
        float v2 = fmaxf(sdist[lane + 32], 0.0f);
        float sum = v1 + v2;
#pragma unroll
        for (int off = 16; off; off >>= 1)
            sum += __shfl_xor_sync(0xffffffffu, sum, off);
        float m = sum * (1.0f / 64.0f);
        float q = (v1 - m) * (v1 - m) + (v2 - m) * (v2 - m);
#pragma unroll
        for (int off = 16; off; off >>= 1)
            q += __shfl_xor_sync(0xffffffffu, q, off);
        if (lane == 0) { stats[0] = m; stats[1] = q; }
    } else if (w == 1) {
        float v1 = fmaxf(10.0f - sdist[64 + lane], 0.0f);
        float v2 = fmaxf(10.0f - sdist[96 + lane], 0.0f);
        float sum = v1 + v2;
#pragma unroll
        for (int off = 16; off; off >>= 1)
            sum += __shfl_xor_sync(0xffffffffu, sum, off);
        float m = sum * (1.0f / 64.0f);
        float q = (v1 - m) * (v1 - m) + (v2 - m) * (v2 - m);
#pragma unroll
        for (int off = 16; off; off >>= 1)
            q += __shfl_xor_sync(0xffffffffu, q, off);
        if (lane == 0) { stats[2] = m; stats[3] = q; }
    }
    __syncthreads();

    if (tid == 0)
        out[20480] = sqrtf(stats[1] / 63.0f) + sqrtf(stats[3] / 63.0f)
                   + stats[0] + stats[2];
}

// ---------------------------------------------------------------------------
extern "C" void kernel_launch(void* const* d_in, const int* in_sizes, int n_in,
                              void* d_out, int out_size)
{
    const float* input_feat  = (const float*)d_in[0];
    const float* rho_coords  = (const float*)d_in[1];
    const float* theta_coord = (const float*)d_in[2];
    const float* mask        = (const float*)d_in[3];
    const float* mu_rho      = (const float*)d_in[4];
    const float* sigma_rho   = (const float*)d_in[5];
    const float* mu_theta    = (const float*)d_in[6];
    const float* sigma_theta = (const float*)d_in[7];
    const float* W_conv      = (const float*)d_in[8];
    const float* b_conv      = (const float*)d_in[9];
    const float* fcc_w       = (const float*)d_in[10];
    const float* fcc_b       = (const float*)d_in[11];
    float* out = (float*)d_out;

    k12<<<S_N, 256>>>(input_feat, rho_coords, theta_coord, mask,
                      mu_rho, sigma_rho, mu_theta, sigma_theta);
    k3_conv<<<dim3(S_N, 2), 320>>>(W_conv);
    k4_fcc<<<S_N / 4, 320>>>(b_conv, fcc_w, fcc_b, out);
    k5_loss<<<1, 1024>>>(out);
}